// round 1
// baseline (speedup 1.0000x reference)
#include <cuda_runtime.h>
#include <math.h>

#define T_TOK 8192
#define DIM   1024
#define FF    4096
#define NE    8

// ---------------- scratch (device globals; no runtime allocation) ----------------
__device__ int   g_cnt[NE];
__device__ int   g_off[NE];
__device__ int   g_pairs[NE][T_TOK];            // value = token*2 + slot
__device__ float g_topw[2 * T_TOK];             // routing weights per (token, slot)
__device__ float g_H[(size_t)2 * T_TOK * FF];   // compacted SwiGLU activations (268 MB)
__device__ float g_y[(size_t)2 * T_TOK * DIM];  // per-pair down-proj output (67 MB)

// ---------------- helpers ----------------
__device__ __forceinline__ unsigned f2tf(float f) {
    unsigned r;
    asm("cvt.rna.tf32.f32 %0, %1;" : "=r"(r) : "f"(f));
    return r;
}

__device__ __forceinline__ void mma_tf32(float acc[4], const unsigned a[4], const unsigned b[2]) {
    asm volatile(
        "mma.sync.aligned.m16n8k8.row.col.f32.tf32.tf32.f32 "
        "{%0,%1,%2,%3}, {%4,%5,%6,%7}, {%8,%9}, {%0,%1,%2,%3};"
        : "+f"(acc[0]), "+f"(acc[1]), "+f"(acc[2]), "+f"(acc[3])
        : "r"(a[0]), "r"(a[1]), "r"(a[2]), "r"(a[3]), "r"(b[0]), "r"(b[1]));
}

// ---------------- k0: zero counts ----------------
__global__ void zero_cnt_kernel() {
    if (threadIdx.x < NE) g_cnt[threadIdx.x] = 0;
}

// ---------------- k1: gate (logits + top2 + softmax + compaction) ----------------
__global__ void gate_kernel(const float* __restrict__ x, const float* __restrict__ gw) {
    int warp = threadIdx.x >> 5, lane = threadIdx.x & 31;
    int t = blockIdx.x * 8 + warp;
    const float* xr = x + (size_t)t * DIM;

    float acc[NE];
#pragma unroll
    for (int e = 0; e < NE; e++) acc[e] = 0.f;

    for (int i = lane; i < DIM; i += 32) {
        float xv = xr[i];
        const float4* g = (const float4*)(gw + (size_t)i * NE);
        float4 g0 = g[0], g1 = g[1];
        acc[0] += xv * g0.x; acc[1] += xv * g0.y; acc[2] += xv * g0.z; acc[3] += xv * g0.w;
        acc[4] += xv * g1.x; acc[5] += xv * g1.y; acc[6] += xv * g1.z; acc[7] += xv * g1.w;
    }
#pragma unroll
    for (int e = 0; e < NE; e++)
#pragma unroll
        for (int o = 16; o; o >>= 1) acc[e] += __shfl_xor_sync(0xFFFFFFFFu, acc[e], o);

    if (lane == 0) {
        int e0 = 0;
#pragma unroll
        for (int e = 1; e < NE; e++) if (acc[e] > acc[e0]) e0 = e;
        int e1 = (e0 == 0) ? 1 : 0;
#pragma unroll
        for (int e = 0; e < NE; e++) if (e != e0 && acc[e] > acc[e1]) e1 = e;

        float d = acc[e1] - acc[e0];          // <= 0
        float ew = __expf(d);
        float inv = 1.f / (1.f + ew);
        g_topw[2 * t + 0] = inv;
        g_topw[2 * t + 1] = ew * inv;

        int p0 = atomicAdd(&g_cnt[e0], 1); g_pairs[e0][p0] = 2 * t + 0;
        int p1 = atomicAdd(&g_cnt[e1], 1); g_pairs[e1][p1] = 2 * t + 1;
    }
}

// ---------------- k2: 8-element exclusive prefix ----------------
__global__ void prefix_kernel() {
    if (threadIdx.x == 0) {
        int s = 0;
        for (int e = 0; e < NE; e++) { g_off[e] = s; s += g_cnt[e]; }
    }
}

// ---------------- k3: fused up-proj  H = silu(Xg@w1) * (Xg@w3) ----------------
// BM=128, BN=64, BK=32; 8 warps in 4x2, each warp 32x32 per accumulator.
__global__ void __launch_bounds__(256) up_kernel(const float* __restrict__ x,
                                                 const float* __restrict__ w1,
                                                 const float* __restrict__ w3) {
    int e = blockIdx.z;
    int cnt = g_cnt[e];
    int m0 = blockIdx.y * 128;
    if (m0 >= cnt) return;
    int n0 = blockIdx.x * 64;

    __shared__ int      toks[128];
    __shared__ unsigned As[128][33];
    __shared__ unsigned B1s[32][65];
    __shared__ unsigned B3s[32][65];

    int tid = threadIdx.x;
    if (tid < 128) {
        int idx = m0 + tid;
        int pair = (idx < cnt) ? g_pairs[e][idx] : g_pairs[e][0];
        toks[tid] = pair >> 1;
    }
    __syncthreads();

    int warp = tid >> 5, lane = tid & 31;
    int wm = warp >> 1, wn = warp & 1;
    int q = lane & 3, gp = lane >> 2;

    float acc1[2][4][4], acc3[2][4][4];
#pragma unroll
    for (int mi = 0; mi < 2; mi++)
#pragma unroll
        for (int ni = 0; ni < 4; ni++)
#pragma unroll
            for (int r = 0; r < 4; r++) { acc1[mi][ni][r] = 0.f; acc3[mi][ni][r] = 0.f; }

    const float* w1b = w1 + (size_t)e * DIM * FF + n0;
    const float* w3b = w3 + (size_t)e * DIM * FF + n0;

    for (int kt = 0; kt < DIM; kt += 32) {
        // A tile: 128 rows x 32 cols (gathered tokens)
#pragma unroll
        for (int p = 0; p < 4; p++) {
            int r = p * 32 + (tid >> 3);
            int c4 = (tid & 7) * 4;
            float4 v = *(const float4*)(x + (size_t)toks[r] * DIM + kt + c4);
            As[r][c4 + 0] = f2tf(v.x); As[r][c4 + 1] = f2tf(v.y);
            As[r][c4 + 2] = f2tf(v.z); As[r][c4 + 3] = f2tf(v.w);
        }
        // B tiles: 32 x 64 from w1 and w3
#pragma unroll
        for (int p = 0; p < 2; p++) {
            int r = p * 16 + (tid >> 4);
            int c4 = (tid & 15) * 4;
            float4 v = *(const float4*)(w1b + (size_t)(kt + r) * FF + c4);
            B1s[r][c4 + 0] = f2tf(v.x); B1s[r][c4 + 1] = f2tf(v.y);
            B1s[r][c4 + 2] = f2tf(v.z); B1s[r][c4 + 3] = f2tf(v.w);
            float4 u = *(const float4*)(w3b + (size_t)(kt + r) * FF + c4);
            B3s[r][c4 + 0] = f2tf(u.x); B3s[r][c4 + 1] = f2tf(u.y);
            B3s[r][c4 + 2] = f2tf(u.z); B3s[r][c4 + 3] = f2tf(u.w);
        }
        __syncthreads();

#pragma unroll
        for (int k0 = 0; k0 < 32; k0 += 8) {
            unsigned a[2][4], b1[4][2], b3[4][2];
#pragma unroll
            for (int mi = 0; mi < 2; mi++) {
                int r = wm * 32 + mi * 16 + gp;
                a[mi][0] = As[r][k0 + q];
                a[mi][1] = As[r + 8][k0 + q];
                a[mi][2] = As[r][k0 + 4 + q];
                a[mi][3] = As[r + 8][k0 + 4 + q];
            }
#pragma unroll
            for (int ni = 0; ni < 4; ni++) {
                int c = wn * 32 + ni * 8 + gp;
                b1[ni][0] = B1s[k0 + q][c];     b1[ni][1] = B1s[k0 + 4 + q][c];
                b3[ni][0] = B3s[k0 + q][c];     b3[ni][1] = B3s[k0 + 4 + q][c];
            }
#pragma unroll
            for (int mi = 0; mi < 2; mi++)
#pragma unroll
                for (int ni = 0; ni < 4; ni++) {
                    mma_tf32(acc1[mi][ni], a[mi], b1[ni]);
                    mma_tf32(acc3[mi][ni], a[mi], b3[ni]);
                }
        }
        __syncthreads();
    }

    // epilogue: SwiGLU + store to compacted H
    int row_off = g_off[e];
#pragma unroll
    for (int mi = 0; mi < 2; mi++)
#pragma unroll
        for (int ni = 0; ni < 4; ni++) {
            int r_lo = wm * 32 + mi * 16 + gp;
            int col = n0 + wn * 32 + ni * 8 + 2 * q;
#pragma unroll
            for (int h = 0; h < 2; h++) {
                int r = r_lo + h * 8;
                int gm = m0 + r;
                if (gm < cnt) {
                    float v1a = acc1[mi][ni][2 * h], v1b = acc1[mi][ni][2 * h + 1];
                    float v3a = acc3[mi][ni][2 * h], v3b = acc3[mi][ni][2 * h + 1];
                    float ha = v3a * (v1a / (1.f + __expf(-v1a)));
                    float hb = v3b * (v1b / (1.f + __expf(-v1b)));
                    *(float2*)(&g_H[(size_t)(row_off + gm) * FF + col]) = make_float2(ha, hb);
                }
            }
        }
}

// ---------------- k4: down-proj  Y[pair] = H @ w2[e] ----------------
__global__ void __launch_bounds__(256) down_kernel(const float* __restrict__ w2) {
    int e = blockIdx.z;
    int cnt = g_cnt[e];
    int m0 = blockIdx.y * 128;
    if (m0 >= cnt) return;
    int n0 = blockIdx.x * 64;
    int row_off = g_off[e];

    __shared__ int      prs[128];
    __shared__ unsigned As[128][33];
    __shared__ unsigned Bs[32][65];

    int tid = threadIdx.x;
    if (tid < 128) {
        int idx = m0 + tid;
        prs[tid] = (idx < cnt) ? g_pairs[e][idx] : -1;
    }
    __syncthreads();

    int warp = tid >> 5, lane = tid & 31;
    int wm = warp >> 1, wn = warp & 1;
    int q = lane & 3, gp = lane >> 2;

    float acc[2][4][4];
#pragma unroll
    for (int mi = 0; mi < 2; mi++)
#pragma unroll
        for (int ni = 0; ni < 4; ni++)
#pragma unroll
            for (int r = 0; r < 4; r++) acc[mi][ni][r] = 0.f;

    const float* w2b = w2 + (size_t)e * FF * DIM + n0;

    for (int kt = 0; kt < FF; kt += 32) {
#pragma unroll
        for (int p = 0; p < 4; p++) {
            int r = p * 32 + (tid >> 3);
            int rc = m0 + r; if (rc >= cnt) rc = cnt - 1;   // clamp (results discarded)
            int c4 = (tid & 7) * 4;
            float4 v = *(const float4*)(&g_H[(size_t)(row_off + rc) * FF + kt + c4]);
            As[r][c4 + 0] = f2tf(v.x); As[r][c4 + 1] = f2tf(v.y);
            As[r][c4 + 2] = f2tf(v.z); As[r][c4 + 3] = f2tf(v.w);
        }
#pragma unroll
        for (int p = 0; p < 2; p++) {
            int r = p * 16 + (tid >> 4);
            int c4 = (tid & 15) * 4;
            float4 v = *(const float4*)(w2b + (size_t)(kt + r) * DIM + c4);
            Bs[r][c4 + 0] = f2tf(v.x); Bs[r][c4 + 1] = f2tf(v.y);
            Bs[r][c4 + 2] = f2tf(v.z); Bs[r][c4 + 3] = f2tf(v.w);
        }
        __syncthreads();

#pragma unroll
        for (int k0 = 0; k0 < 32; k0 += 8) {
            unsigned a[2][4], b[4][2];
#pragma unroll
            for (int mi = 0; mi < 2; mi++) {
                int r = wm * 32 + mi * 16 + gp;
                a[mi][0] = As[r][k0 + q];
                a[mi][1] = As[r + 8][k0 + q];
                a[mi][2] = As[r][k0 + 4 + q];
                a[mi][3] = As[r + 8][k0 + 4 + q];
            }
#pragma unroll
            for (int ni = 0; ni < 4; ni++) {
                int c = wn * 32 + ni * 8 + gp;
                b[ni][0] = Bs[k0 + q][c];
                b[ni][1] = Bs[k0 + 4 + q][c];
            }
#pragma unroll
            for (int mi = 0; mi < 2; mi++)
#pragma unroll
                for (int ni = 0; ni < 4; ni++)
                    mma_tf32(acc[mi][ni], a[mi], b[ni]);
        }
        __syncthreads();
    }

    // epilogue: scatter rows to per-pair slots (no atomics, deterministic)
#pragma unroll
    for (int mi = 0; mi < 2; mi++)
#pragma unroll
        for (int ni = 0; ni < 4; ni++) {
            int r_lo = wm * 32 + mi * 16 + gp;
            int col = n0 + wn * 32 + ni * 8 + 2 * q;
#pragma unroll
            for (int h = 0; h < 2; h++) {
                int r = r_lo + h * 8;
                int pair = prs[r];
                if (pair >= 0) {
                    *(float2*)(&g_y[(size_t)pair * DIM + col]) =
                        make_float2(acc[mi][ni][2 * h], acc[mi][ni][2 * h + 1]);
                }
            }
        }
}

// ---------------- k5: combine out[t] = w0*Y[2t] + w1*Y[2t+1] ----------------
__global__ void combine_kernel(float* __restrict__ out) {
    int t = blockIdx.x;
    int d4 = threadIdx.x;   // 256 threads = 1024/4 float4s
    float w0 = g_topw[2 * t], w1 = g_topw[2 * t + 1];
    const float4* y0 = (const float4*)&g_y[(size_t)(2 * t) * DIM];
    const float4* y1 = (const float4*)&g_y[(size_t)(2 * t + 1) * DIM];
    float4 a = y0[d4], b = y1[d4];
    float4 r;
    r.x = w0 * a.x + w1 * b.x;
    r.y = w0 * a.y + w1 * b.y;
    r.z = w0 * a.z + w1 * b.z;
    r.w = w0 * a.w + w1 * b.w;
    ((float4*)(out + (size_t)t * DIM))[d4] = r;
}

// ---------------- entry ----------------
extern "C" void kernel_launch(void* const* d_in, const int* in_sizes, int n_in,
                              void* d_out, int out_size) {
    const float* x  = (const float*)d_in[0];
    const float* gw = (const float*)d_in[1];
    const float* w1 = (const float*)d_in[2];
    const float* w3 = (const float*)d_in[3];
    const float* w2 = (const float*)d_in[4];
    float* out = (float*)d_out;

    zero_cnt_kernel<<<1, 32>>>();
    gate_kernel<<<T_TOK / 8, 256>>>(x, gw);
    prefix_kernel<<<1, 32>>>();
    up_kernel<<<dim3(FF / 64, T_TOK / 128, NE), 256>>>(x, w1, w3);
    down_kernel<<<dim3(DIM / 64, T_TOK / 128, NE), 256>>>(w2);
    combine_kernel<<<T_TOK, 256>>>(out);
}

// round 4
// speedup vs baseline: 5.2579x; 5.2579x over previous
#include <cuda_runtime.h>
#include <cuda_fp16.h>
#include <math.h>
#include <cstdint>

#define T_TOK 8192
#define DIM   1024
#define FF    4096
#define NE    8

// ---------------- scratch (device globals; no runtime allocation) ----------------
__device__ int    g_cnt[NE];
__device__ int    g_off[NE];
__device__ int    g_pairs[NE][T_TOK];            // value = token*2 + slot
__device__ float  g_topw[2 * T_TOK];             // routing weights per (token, slot)
__device__ __align__(256) __half g_xh[(size_t)T_TOK * DIM];     // fp16 copy of x
__device__ __align__(256) __half g_w1h[(size_t)NE * DIM * FF];  // fp16 weights
__device__ __align__(256) __half g_w3h[(size_t)NE * DIM * FF];
__device__ __align__(256) __half g_w2h[(size_t)NE * FF * DIM];
__device__ __align__(256) __half g_H[(size_t)2 * T_TOK * FF];   // compacted SwiGLU acts
__device__ __align__(256) float  g_y[(size_t)2 * T_TOK * DIM];  // per-pair down output

// ---------------- helpers ----------------
__device__ __forceinline__ uint32_t s2u(const void* p) {
    uint32_t a;
    asm("{ .reg .u64 t; cvta.to.shared.u64 t, %1; cvt.u32.u64 %0, t; }" : "=r"(a) : "l"(p));
    return a;
}
#define SWZ(x) ((x) ^ ((((uint32_t)(x)) >> 3) & 0x70u))

#define CP16(dst, src) \
    asm volatile("cp.async.cg.shared.global [%0], [%1], 16;" :: "r"(dst), "l"(src) : "memory")
#define CP_COMMIT() asm volatile("cp.async.commit_group;" ::: "memory")
#define CP_WAIT1()  asm volatile("cp.async.wait_group 1;" ::: "memory")
#define CP_WAIT0()  asm volatile("cp.async.wait_group 0;" ::: "memory")

__device__ __forceinline__ void ldsm4(uint32_t r[4], uint32_t addr) {
    asm volatile("ldmatrix.sync.aligned.m8n8.x4.shared.b16 {%0,%1,%2,%3}, [%4];"
        : "=r"(r[0]), "=r"(r[1]), "=r"(r[2]), "=r"(r[3]) : "r"(addr));
}
__device__ __forceinline__ void ldsm4t(uint32_t r[4], uint32_t addr) {
    asm volatile("ldmatrix.sync.aligned.m8n8.x4.trans.shared.b16 {%0,%1,%2,%3}, [%4];"
        : "=r"(r[0]), "=r"(r[1]), "=r"(r[2]), "=r"(r[3]) : "r"(addr));
}
__device__ __forceinline__ void mma16816(float c[4], const uint32_t a[4], const uint32_t b[2]) {
    asm volatile(
        "mma.sync.aligned.m16n8k16.row.col.f32.f16.f16.f32 "
        "{%0,%1,%2,%3}, {%4,%5,%6,%7}, {%8,%9}, {%0,%1,%2,%3};"
        : "+f"(c[0]), "+f"(c[1]), "+f"(c[2]), "+f"(c[3])
        : "r"(a[0]), "r"(a[1]), "r"(a[2]), "r"(a[3]), "r"(b[0]), "r"(b[1]));
}

// ---------------- k0: zero counts ----------------
__global__ void zero_cnt_kernel() {
    if (threadIdx.x < NE) g_cnt[threadIdx.x] = 0;
}

// ---------------- convert fp32 -> fp16 into device-global caches ----------------
// which: 0=x, 1=w1, 2=w3, 3=w2
__global__ void cvt_kernel(const float* __restrict__ in, int which, int n4) {
    int i = blockIdx.x * 256 + threadIdx.x;
    if (i >= n4) return;
    __half* out = (which == 0) ? g_xh : (which == 1) ? g_w1h : (which == 2) ? g_w3h : g_w2h;
    float4 v = ((const float4*)in)[i];
    __half2 h0 = __float22half2_rn(make_float2(v.x, v.y));
    __half2 h1 = __float22half2_rn(make_float2(v.z, v.w));
    ((__half2*)out)[2 * i + 0] = h0;
    ((__half2*)out)[2 * i + 1] = h1;
}

// ---------------- k1: gate ----------------
__global__ void gate_kernel(const float* __restrict__ x, const float* __restrict__ gw) {
    int warp = threadIdx.x >> 5, lane = threadIdx.x & 31;
    int t = blockIdx.x * 8 + warp;
    const float* xr = x + (size_t)t * DIM;

    float acc[NE];
#pragma unroll
    for (int e = 0; e < NE; e++) acc[e] = 0.f;

    for (int i = lane; i < DIM; i += 32) {
        float xv = xr[i];
        const float4* g = (const float4*)(gw + (size_t)i * NE);
        float4 g0 = g[0], g1 = g[1];
        acc[0] += xv * g0.x; acc[1] += xv * g0.y; acc[2] += xv * g0.z; acc[3] += xv * g0.w;
        acc[4] += xv * g1.x; acc[5] += xv * g1.y; acc[6] += xv * g1.z; acc[7] += xv * g1.w;
    }
#pragma unroll
    for (int e = 0; e < NE; e++)
#pragma unroll
        for (int o = 16; o; o >>= 1) acc[e] += __shfl_xor_sync(0xFFFFFFFFu, acc[e], o);

    if (lane == 0) {
        int e0 = 0;
#pragma unroll
        for (int e = 1; e < NE; e++) if (acc[e] > acc[e0]) e0 = e;
        int e1 = (e0 == 0) ? 1 : 0;
#pragma unroll
        for (int e = 0; e < NE; e++) if (e != e0 && acc[e] > acc[e1]) e1 = e;

        float d = acc[e1] - acc[e0];
        float ew = __expf(d);
        float inv = 1.f / (1.f + ew);
        g_topw[2 * t + 0] = inv;
        g_topw[2 * t + 1] = ew * inv;

        int p0 = atomicAdd(&g_cnt[e0], 1); g_pairs[e0][p0] = 2 * t + 0;
        int p1 = atomicAdd(&g_cnt[e1], 1); g_pairs[e1][p1] = 2 * t + 1;
    }
}

// ---------------- k2: prefix ----------------
__global__ void prefix_kernel() {
    if (threadIdx.x == 0) {
        int s = 0;
        for (int e = 0; e < NE; e++) { g_off[e] = s; s += g_cnt[e]; }
    }
}

// ======================= k3: up  H = silu(Xg@w1)*(Xg@w3) =======================
// BM=128, BN=64 (per gemm, two gemms), BK=64 halves. 8 warps (4M x 2N),
// warp tile 32M x 32N per gemm. Double-buffered cp.async pipeline.
// smem: toks @0 (512B), stage p at 1024 + p*32768: A(16K), B1(8K), B3(8K).
#define UP_ST  32768u
#define UP_AO  1024u
#define UP_B1O (1024u + 16384u)
#define UP_B3O (1024u + 24576u)

__device__ __forceinline__ void up_issue(int i, uint32_t sb, const int* toks,
                                         const __half* w1b, const __half* w3b,
                                         int r_, int ch_) {
    uint32_t ab  = UP_AO  + (i & 1) * UP_ST;
    uint32_t b1b = UP_B1O + (i & 1) * UP_ST;
    uint32_t b3b = UP_B3O + (i & 1) * UP_ST;
    int kt = i * 64;
#pragma unroll
    for (int j = 0; j < 4; j++) {
        int r = r_ + 32 * j;
        const __half* src = g_xh + (size_t)toks[r] * DIM + kt + ch_ * 8;
        CP16(sb + SWZ(ab + r * 128 + ch_ * 16), src);
    }
#pragma unroll
    for (int j = 0; j < 2; j++) {
        int k = r_ + 32 * j;
        CP16(sb + SWZ(b1b + k * 128 + ch_ * 16), w1b + (size_t)(kt + k) * FF + ch_ * 8);
        CP16(sb + SWZ(b3b + k * 128 + ch_ * 16), w3b + (size_t)(kt + k) * FF + ch_ * 8);
    }
    CP_COMMIT();
}

__global__ void __launch_bounds__(256, 2) up_kernel() {
    int e = blockIdx.z;
    int cnt = g_cnt[e];
    int m0 = blockIdx.y * 128;
    if (m0 >= cnt) return;
    int n0 = blockIdx.x * 64;

    extern __shared__ unsigned char sm[];
    uint32_t sb = s2u(sm);
    int* toks = (int*)sm;

    int tid = threadIdx.x, wid = tid >> 5, lane = tid & 31;
    if (tid < 128) {
        int idx = m0 + tid;
        toks[tid] = ((idx < cnt) ? g_pairs[e][idx] : g_pairs[e][0]) >> 1;
    }
    __syncthreads();

    const __half* w1b = g_w1h + (size_t)e * DIM * FF + n0;
    const __half* w3b = g_w3h + (size_t)e * DIM * FF + n0;

    int r_ = tid >> 3, ch_ = tid & 7;
    int wm = wid >> 1, wn = wid & 1;

    float acc1[2][4][4], acc3[2][4][4];
#pragma unroll
    for (int mi = 0; mi < 2; mi++)
#pragma unroll
        for (int nj = 0; nj < 4; nj++)
#pragma unroll
            for (int r = 0; r < 4; r++) { acc1[mi][nj][r] = 0.f; acc3[mi][nj][r] = 0.f; }

    up_issue(0, sb, toks, w1b, w3b, r_, ch_);

    int mloc = lane >> 3, rloc = lane & 7;
#pragma unroll 1
    for (int i = 0; i < DIM / 64; i++) {
        if (i + 1 < DIM / 64) { up_issue(i + 1, sb, toks, w1b, w3b, r_, ch_); CP_WAIT1(); }
        else                  { CP_WAIT0(); }
        __syncthreads();

        uint32_t ab  = UP_AO  + (i & 1) * UP_ST;
        uint32_t b1b = UP_B1O + (i & 1) * UP_ST;
        uint32_t b3b = UP_B3O + (i & 1) * UP_ST;
#pragma unroll
        for (int kk = 0; kk < 4; kk++) {
            uint32_t a[2][4];
#pragma unroll
            for (int mi = 0; mi < 2; mi++)
                ldsm4(a[mi], sb + SWZ(ab + (wm * 32 + mi * 16 + (lane & 15)) * 128
                                         + kk * 32 + (lane >> 4) * 16));
            uint32_t b1[2][4], b3[2][4];
#pragma unroll
            for (int ni = 0; ni < 2; ni++) {
                uint32_t off = (kk * 16 + (mloc & 1) * 8 + rloc) * 128
                             + (wn * 32 + ni * 16 + (mloc >> 1) * 8) * 2;
                ldsm4t(b1[ni], sb + SWZ(b1b + off));
                ldsm4t(b3[ni], sb + SWZ(b3b + off));
            }
#pragma unroll
            for (int mi = 0; mi < 2; mi++)
#pragma unroll
                for (int nj = 0; nj < 4; nj++) {
                    mma16816(acc1[mi][nj], a[mi], &b1[nj >> 1][(nj & 1) * 2]);
                    mma16816(acc3[mi][nj], a[mi], &b3[nj >> 1][(nj & 1) * 2]);
                }
        }
        __syncthreads();
    }

    // epilogue: SwiGLU -> g_H (fp16)
    int gp = lane >> 2, q = lane & 3;
    int row_off = g_off[e];
#pragma unroll
    for (int mi = 0; mi < 2; mi++)
#pragma unroll
        for (int nj = 0; nj < 4; nj++) {
            int row0 = m0 + wm * 32 + mi * 16 + gp;
            int col = n0 + wn * 32 + nj * 8 + 2 * q;
#pragma unroll
            for (int h = 0; h < 2; h++) {
                int gm = row0 + 8 * h;
                if (gm < cnt) {
                    float v1a = acc1[mi][nj][2 * h], v1b = acc1[mi][nj][2 * h + 1];
                    float v3a = acc3[mi][nj][2 * h], v3b = acc3[mi][nj][2 * h + 1];
                    float ha = v3a * (v1a / (1.f + __expf(-v1a)));
                    float hb = v3b * (v1b / (1.f + __expf(-v1b)));
                    __half2 hv = __float22half2_rn(make_float2(ha, hb));
                    *(__half2*)(&g_H[(size_t)(row_off + gm) * FF + col]) = hv;
                }
            }
        }
}

// ======================= k4: down  Y[pair] = H @ w2[e] =======================
// BM=128, BN=128, BK=64. 8 warps (4M x 2N), warp tile 32M x 64N.
// smem: prs @0, rowsA @512, stage p at 1024 + p*32768: A(16K), B(16K as two
// 8K sub-tiles of 64 n-halves each, 128B SW128 rows).
#define DN_ST 32768u
#define DN_AO 1024u
#define DN_BO (1024u + 16384u)

__device__ __forceinline__ void dn_issue(int i, uint32_t sb, const int* rows,
                                         const __half* w2b, int r_, int ch_,
                                         int ra_, int ca_) {
    uint32_t ab = DN_AO + (i & 1) * DN_ST;
    uint32_t bb = DN_BO + (i & 1) * DN_ST;
    int kt = i * 64;
#pragma unroll
    for (int j = 0; j < 4; j++) {
        int r = r_ + 32 * j;
        const __half* src = g_H + (size_t)rows[r] * FF + kt + ch_ * 8;
        CP16(sb + SWZ(ab + r * 128 + ch_ * 16), src);
    }
#pragma unroll
    for (int j = 0; j < 4; j++) {
        int k = ra_ + 16 * j;
        const __half* src = w2b + (size_t)(kt + k) * DIM + ca_ * 8;
        uint32_t dst = bb + (ca_ >> 3) * 8192 + k * 128 + (ca_ & 7) * 16;
        CP16(sb + SWZ(dst), src);
    }
    CP_COMMIT();
}

__global__ void __launch_bounds__(256, 2) down_kernel() {
    int e = blockIdx.z;
    int cnt = g_cnt[e];
    int m0 = blockIdx.y * 128;
    if (m0 >= cnt) return;
    int n0 = blockIdx.x * 128;
    int row_off = g_off[e];

    extern __shared__ unsigned char sm[];
    uint32_t sb = s2u(sm);
    int* prs   = (int*)sm;          // pair index per row (-1 = pad)
    int* rowsA = (int*)(sm + 512);  // clamped compacted-H row per tile row

    int tid = threadIdx.x, wid = tid >> 5, lane = tid & 31;
    if (tid < 128) {
        int idx = m0 + tid;
        prs[tid]   = (idx < cnt) ? g_pairs[e][idx] : -1;
        rowsA[tid] = row_off + ((idx < cnt) ? idx : (cnt - 1));
    }
    __syncthreads();

    const __half* w2b = g_w2h + (size_t)e * FF * DIM + n0;

    int r_ = tid >> 3, ch_ = tid & 7;       // A staging
    int ra_ = tid >> 4, ca_ = tid & 15;     // B staging
    int wm = wid >> 1, wn = wid & 1;

    float acc[2][8][4];
#pragma unroll
    for (int mi = 0; mi < 2; mi++)
#pragma unroll
        for (int nj = 0; nj < 8; nj++)
#pragma unroll
            for (int r = 0; r < 4; r++) acc[mi][nj][r] = 0.f;

    dn_issue(0, sb, rowsA, w2b, r_, ch_, ra_, ca_);

    int mloc = lane >> 3, rloc = lane & 7;
#pragma unroll 1
    for (int i = 0; i < FF / 64; i++) {
        if (i + 1 < FF / 64) { dn_issue(i + 1, sb, rowsA, w2b, r_, ch_, ra_, ca_); CP_WAIT1(); }
        else                 { CP_WAIT0(); }
        __syncthreads();

        uint32_t ab = DN_AO + (i & 1) * DN_ST;
        uint32_t bb = DN_BO + (i & 1) * DN_ST + wn * 8192;  // this warp's 64-n sub-tile
#pragma unroll
        for (int kk = 0; kk < 4; kk++) {
            uint32_t a[2][4];
#pragma unroll
            for (int mi = 0; mi < 2; mi++)
                ldsm4(a[mi], sb + SWZ(ab + (wm * 32 + mi * 16 + (lane & 15)) * 128
                                         + kk * 32 + (lane >> 4) * 16));
            uint32_t b[4][4];
#pragma unroll
            for (int ni = 0; ni < 4; ni++) {
                uint32_t off = (kk * 16 + (mloc & 1) * 8 + rloc) * 128
                             + (ni * 16 + (mloc >> 1) * 8) * 2;
                ldsm4t(b[ni], sb + SWZ(bb + off));
            }
#pragma unroll
            for (int mi = 0; mi < 2; mi++)
#pragma unroll
                for (int nj = 0; nj < 8; nj++)
                    mma16816(acc[mi][nj], a[mi], &b[nj >> 1][(nj & 1) * 2]);
        }
        __syncthreads();
    }

    // epilogue: scatter float2 rows to per-pair slots
    int gp = lane >> 2, q = lane & 3;
#pragma unroll
    for (int mi = 0; mi < 2; mi++)
#pragma unroll
        for (int nj = 0; nj < 8; nj++) {
            int r0 = wm * 32 + mi * 16 + gp;
            int col = n0 + wn * 64 + nj * 8 + 2 * q;
#pragma unroll
            for (int h = 0; h < 2; h++) {
                int pair = prs[r0 + 8 * h];
                if (pair >= 0) {
                    *(float2*)(&g_y[(size_t)pair * DIM + col]) =
                        make_float2(acc[mi][nj][2 * h], acc[mi][nj][2 * h + 1]);
                }
            }
        }
}

// ---------------- k5: combine ----------------
__global__ void combine_kernel(float* __restrict__ out) {
    int t = blockIdx.x;
    int d4 = threadIdx.x;
    float w0 = g_topw[2 * t], w1 = g_topw[2 * t + 1];
    const float4* y0 = (const float4*)&g_y[(size_t)(2 * t) * DIM];
    const float4* y1 = (const float4*)&g_y[(size_t)(2 * t + 1) * DIM];
    float4 a = y0[d4], b = y1[d4];
    float4 r;
    r.x = w0 * a.x + w1 * b.x;
    r.y = w0 * a.y + w1 * b.y;
    r.z = w0 * a.z + w1 * b.z;
    r.w = w0 * a.w + w1 * b.w;
    ((float4*)(out + (size_t)t * DIM))[d4] = r;
}

// ---------------- entry ----------------
extern "C" void kernel_launch(void* const* d_in, const int* in_sizes, int n_in,
                              void* d_out, int out_size) {
    const float* x  = (const float*)d_in[0];
    const float* gw = (const float*)d_in[1];
    const float* w1 = (const float*)d_in[2];
    const float* w3 = (const float*)d_in[3];
    const float* w2 = (const float*)d_in[4];
    float* out = (float*)d_out;

    const int UP_SMEM   = 1024 + 2 * 32768;   // 66560
    const int DOWN_SMEM = 1024 + 2 * 32768;   // 66560
    cudaFuncSetAttribute(up_kernel,   cudaFuncAttributeMaxDynamicSharedMemorySize, UP_SMEM);
    cudaFuncSetAttribute(down_kernel, cudaFuncAttributeMaxDynamicSharedMemorySize, DOWN_SMEM);

    const int W4 = NE * DIM * FF / 4;   // 8388608
    const int X4 = T_TOK * DIM / 4;     // 2097152

    zero_cnt_kernel<<<1, 32>>>();
    gate_kernel<<<T_TOK / 8, 256>>>(x, gw);
    prefix_kernel<<<1, 32>>>();
    cvt_kernel<<<X4 / 256, 256>>>(x,  0, X4);
    cvt_kernel<<<W4 / 256, 256>>>(w1, 1, W4);
    cvt_kernel<<<W4 / 256, 256>>>(w3, 2, W4);
    cvt_kernel<<<W4 / 256, 256>>>(w2, 3, W4);
    up_kernel<<<dim3(FF / 64, T_TOK / 128, NE), 256, UP_SMEM>>>();
    down_kernel<<<dim3(DIM / 128, T_TOK / 128, NE), 256, DOWN_SMEM>>>();
    combine_kernel<<<T_TOK, 256>>>(out);
}